// round 1
// baseline (speedup 1.0000x reference)
#include <cuda_runtime.h>

#define RES    16
#define HID    32
#define CONDN  10
#define NOUT   256
#define BLOCK  256
#define WARPS  8
#define T      4
#define FULLM  0xffffffffu
#define EPSF   1e-12f

// ---- shared layout (float offsets) ----
#define OFF_W0   0
#define OFF_B0   (OFF_W0 + CONDN*HID)        // 320
#define OFF_W1   (OFF_B0 + HID)              // 352
#define OFF_B1   (OFF_W1 + HID*HID)          // 1376
#define OFF_W2   (OFF_B1 + HID)              // 1408
#define OFF_B2   (OFF_W2 + HID*HID)          // 2432
#define OFF_W3   (OFF_B2 + HID)              // 2464 (float2 region, 4096 float2)
#define OFF_B3   (OFF_W3 + 2*HID*128)        // 10656 (float2 region, 128 float2)
#define OFF_HIST (OFF_B3 + 2*128)            // 10912
#define HROW     20                          // padded row stride (16 rows)
#define HIST_STRIDE (RES*HROW)               // 320 floats per sample
#define SMEM_FLOATS (OFF_HIST + WARPS*T*HIST_STRIDE)   // 21152
#define SMEM_BYTES  (SMEM_FLOATS*4)                    // 84608

// packed fp32x2 FMA (sm_100+): the only way to get FFMA2 in SASS
__device__ __forceinline__ float2 ffma2(float2 a, float2 b, float2 c) {
    float2 d;
    asm("fma.rn.f32x2 %0, %1, %2, %3;"
        : "=l"(reinterpret_cast<unsigned long long&>(d))
        : "l"(reinterpret_cast<unsigned long long&>(a)),
          "l"(reinterpret_cast<unsigned long long&>(b)),
          "l"(reinterpret_cast<unsigned long long&>(c)));
    return d;
}

__device__ __forceinline__ float softplusf(float z) {
    float a = fabsf(z);
    float e = __expf(-a);
    float l = __logf(1.0f + e);
    return fmaxf(z, 0.0f) + l;
}

// inclusive scan over 16-lane halves (both halves hold duplicate data)
__device__ __forceinline__ float scan16(float v, int yl) {
    #pragma unroll
    for (int off = 1; off < 16; off <<= 1) {
        float u = __shfl_up_sync(FULLM, v, off);
        if (yl >= off) v += u;
    }
    return v;
}

__global__ __launch_bounds__(BLOCK, 2)
void hist2d_inv_kernel(
    const float* __restrict__ wi,  const float* __restrict__ cond,
    const float* __restrict__ w0,  const float* __restrict__ b0,
    const float* __restrict__ w1,  const float* __restrict__ b1,
    const float* __restrict__ w2,  const float* __restrict__ b2,
    const float* __restrict__ w3,  const float* __restrict__ b3,
    float* __restrict__ out, int B)
{
    extern __shared__ float sm[];
    float2* w3p = (float2*)(sm + OFF_W3);
    float2* b3p = (float2*)(sm + OFF_B3);
    const int tid = threadIdx.x;

    // ---- cooperative weight staging ----
    for (int i = tid; i < CONDN*HID; i += BLOCK) sm[OFF_W0+i] = w0[i];
    for (int i = tid; i < HID; i += BLOCK) {
        sm[OFF_B0+i] = b0[i]; sm[OFF_B1+i] = b1[i]; sm[OFF_B2+i] = b2[i];
    }
    for (int i = tid; i < HID*HID; i += BLOCK) {
        sm[OFF_W1+i] = w1[i]; sm[OFF_W2+i] = w2[i];
    }
    // w3 pre-permuted into output pairs (m, m+32): w3p[k*128 + p*32 + j]
    for (int i = tid; i < HID*128; i += BLOCK) {
        int k = i >> 7, r = i & 127, p = r >> 5, j = r & 31;
        w3p[i] = make_float2(w3[k*NOUT + p*64 + j], w3[k*NOUT + p*64 + 32 + j]);
    }
    for (int i = tid; i < 128; i += BLOCK) {
        int p = i >> 5, j = i & 31;
        b3p[i] = make_float2(b3[p*64 + j], b3[p*64 + 32 + j]);
    }
    __syncthreads();

    const int lane = tid & 31;
    const int warp = tid >> 5;
    float* hist = sm + OFF_HIST + warp * T * HIST_STRIDE;
    const int gwarp  = blockIdx.x * WARPS + warp;
    const int nwarps = gridDim.x * WARPS;

    for (int s0 = gwarp * T; s0 < B; s0 += nwarps * T) {
        // ---- load cond (lane i holds cond[s][i] for i<10) ----
        float c[T];
        #pragma unroll
        for (int t = 0; t < T; t++) {
            int s = min(s0 + t, B - 1);
            c[t] = (lane < CONDN) ? cond[s*CONDN + lane] : 0.0f;
        }

        // ---- layer 0: 10 -> 32 ----
        float h[T];
        {
            float acc[T];
            float bb = sm[OFF_B0 + lane];
            #pragma unroll
            for (int t = 0; t < T; t++) acc[t] = bb;
            #pragma unroll
            for (int i = 0; i < CONDN; i++) {
                float w = sm[OFF_W0 + i*HID + lane];
                #pragma unroll
                for (int t = 0; t < T; t++)
                    acc[t] = fmaf(__shfl_sync(FULLM, c[t], i), w, acc[t]);
            }
            #pragma unroll
            for (int t = 0; t < T; t++) h[t] = fmaxf(acc[t], 0.0f);
        }
        // ---- layers 1,2: 32 -> 32 ----
        #pragma unroll
        for (int L = 0; L < 2; L++) {
            const float* W = sm + (L == 0 ? OFF_W1 : OFF_W2);
            const float* Bv = sm + (L == 0 ? OFF_B1 : OFF_B2);
            float acc[T];
            float bb = Bv[lane];
            #pragma unroll
            for (int t = 0; t < T; t++) acc[t] = bb;
            #pragma unroll
            for (int k = 0; k < HID; k++) {
                float w = W[k*HID + lane];
                #pragma unroll
                for (int t = 0; t < T; t++)
                    acc[t] = fmaf(__shfl_sync(FULLM, h[t], k), w, acc[t]);
            }
            #pragma unroll
            for (int t = 0; t < T; t++) h[t] = fmaxf(acc[t], 0.0f);
        }

        // ---- layer 3: 32 -> 256, FFMA2 packed (outputs m=64p+lane, m+32) ----
        float2 acc3[T][4];
        #pragma unroll
        for (int p = 0; p < 4; p++) {
            float2 bb = b3p[p*32 + lane];
            #pragma unroll
            for (int t = 0; t < T; t++) acc3[t][p] = bb;
        }
        #pragma unroll
        for (int k = 0; k < HID; k++) {
            float2 wv[4];
            #pragma unroll
            for (int p = 0; p < 4; p++) wv[p] = w3p[k*128 + p*32 + lane];
            #pragma unroll
            for (int t = 0; t < T; t++) {
                float hk = __shfl_sync(FULLM, h[t], k);
                float2 hh = make_float2(hk, hk);
                #pragma unroll
                for (int p = 0; p < 4; p++) acc3[t][p] = ffma2(wv[p], hh, acc3[t][p]);
            }
        }

        __syncwarp();   // previous iteration's readers done before overwriting hist

        // ---- softplus + stage unnormalized hist into padded SMEM ----
        #pragma unroll
        for (int t = 0; t < T; t++) {
            float* Ht = hist + t * HIST_STRIDE;
            #pragma unroll
            for (int p = 0; p < 4; p++) {
                float v0 = softplusf(acc3[t][p].x);   // m0 = 64p + lane
                float v1 = softplusf(acc3[t][p].y);   // m1 = m0 + 32
                int m0 = p*64 + lane;
                Ht[(m0 >> 4)*HROW + (m0 & 15)] = v0;
                int m1 = m0 + 32;
                Ht[(m1 >> 4)*HROW + (m1 & 15)] = v1;
            }
        }
        __syncwarp();

        // ---- inverse-CDF sampling, one sample at a time (warp-cooperative) ----
        const int yl = lane & 15;
        #pragma unroll
        for (int t = 0; t < T; t++) {
            int s = s0 + t;
            bool valid = (s < B);
            int sc = min(s, B - 1);
            float2 uu = *(const float2*)(wi + 2*sc);
            float ux = uu.x, uy = uu.y;
            const float* Ht = hist + t * HIST_STRIDE;

            // row sums (lane yl handles row yl; both halves duplicate)
            const float4* r4 = (const float4*)(Ht + yl*HROW);
            float4 a = r4[0], bq = r4[1], cq = r4[2], dq = r4[3];
            float rs = ((a.x + a.y) + (a.z + a.w)) + ((bq.x + bq.y) + (bq.z + bq.w))
                     + ((cq.x + cq.y) + (cq.z + cq.w)) + ((dq.x + dq.y) + (dq.z + dq.w));

            float C = scan16(rs, yl);                  // unnormalized cdf_y
            float S = __shfl_sync(FULLM, C, 15);
            float invS = 1.0f / fmaxf(S, EPSF);
            float ty = uy * fmaxf(S, EPSF);            // compare C < uy*S  <=>  cdf_y < uy
            unsigned my = __ballot_sync(FULLM, C < ty) & 0xFFFFu;
            int iy = __popc(my); if (iy > 15) iy = 15;
            float Cprev = __shfl_sync(FULLM, C, (iy > 0) ? (iy - 1) : 0);
            if (iy == 0) Cprev = 0.0f;
            float py = __shfl_sync(FULLM, rs, iy);     // unnormalized pdf_y[iy] > 0
            float yout = ((float)iy + (uy - Cprev*invS) / fmaxf(py*invS, EPSF)) * (1.0f/RES);

            // selected row: cumsum over x (normalization by S cancels)
            float vr = Ht[iy*HROW + yl];
            float D = scan16(vr, yl);
            float tx = ux * py;                        // compare D < ux*py <=> cdf_x < ux
            unsigned mx = __ballot_sync(FULLM, D < tx) & 0xFFFFu;
            int ix = __popc(mx); if (ix > 15) ix = 15;
            float Dprev = __shfl_sync(FULLM, D, (ix > 0) ? (ix - 1) : 0);
            if (ix == 0) Dprev = 0.0f;
            float px = __shfl_sync(FULLM, vr, ix);
            float invpy = 1.0f / py;
            float xout = ((float)ix + (ux - Dprev*invpy) / fmaxf(px*invpy, EPSF)) * (1.0f/RES);
            float pdf = px * invS * ((float)(RES*RES) * 0.25f);

            if (valid && lane == 0) {
                *(float2*)(out + 2*s) = make_float2(xout*2.0f - 1.0f, yout*2.0f - 1.0f);
                out[2*B + s] = pdf;
            }
        }
    }
}

extern "C" void kernel_launch(void* const* d_in, const int* in_sizes, int n_in,
                              void* d_out, int out_size)
{
    const float* wi   = (const float*)d_in[0];
    const float* cond = (const float*)d_in[1];
    const float* w0   = (const float*)d_in[2];
    const float* b0   = (const float*)d_in[3];
    const float* w1   = (const float*)d_in[4];
    const float* b1   = (const float*)d_in[5];
    const float* w2   = (const float*)d_in[6];
    const float* b2   = (const float*)d_in[7];
    const float* w3   = (const float*)d_in[8];
    const float* b3   = (const float*)d_in[9];
    // d_in[10] = inverse flag (always 1 for this problem)

    int B = in_sizes[0] / 2;

    cudaFuncSetAttribute(hist2d_inv_kernel,
                         cudaFuncAttributeMaxDynamicSharedMemorySize, SMEM_BYTES);

    // 2 CTAs/SM target on 152-SM GB300; grid-stride loop handles the tail.
    hist2d_inv_kernel<<<304, BLOCK, SMEM_BYTES>>>(
        wi, cond, w0, b0, w1, b1, w2, b2, w3, b3, (float*)d_out, B);
}

// round 3
// speedup vs baseline: 1.1580x; 1.1580x over previous
#include <cuda_runtime.h>

#define RES    16
#define HID    32
#define CONDN  10
#define NOUT   256
#define BLOCK  128
#define WARPS  4
#define T      8
#define PAIRS  4
#define FULLM  0xffffffffu
#define EPSF   1e-12f
#define HROW   20
#define HIST_STRIDE (RES*HROW)   // 320

// ---- shared layout (float offsets) ----
#define OFF_W0D  0                      // 10*32 float2 dup = 640 f
#define OFF_B0D  (OFF_W0D + 640)       // 64 f
#define OFF_W1D  (OFF_B0D + 64)        // 2048 f
#define OFF_B1D  (OFF_W1D + 2048)      // 64 f
#define OFF_W2D  (OFF_B1D + 64)        // 2048 f
#define OFF_B2D  (OFF_W2D + 2048)      // 64 f
#define OFF_W3P  (OFF_B2D + 64)        // 32*128 float2 = 8192 f
#define OFF_B3P  (OFF_W3P + 8192)      // 256 f
#define OFF_WARP (OFF_B3P + 256)       // 13376
#define WARP_COND 0                     // float2[4][10] = 80 f
#define WARP_H    80                    // float2[4][32] = 256 f
#define WARP_HIST 336                   // 8*320 = 2560 f
#define WARP_SIZE_F (WARP_HIST + T*HIST_STRIDE)      // 2896
#define SMEM_FLOATS (OFF_WARP + WARPS*WARP_SIZE_F)   // 24960
#define SMEM_BYTES  (SMEM_FLOATS*4)                  // 99840

// packed fp32x2 FMA (sm_100+): FFMA2 in SASS
__device__ __forceinline__ float2 ffma2(float2 a, float2 b, float2 c) {
    float2 d;
    asm("fma.rn.f32x2 %0, %1, %2, %3;"
        : "=l"(reinterpret_cast<unsigned long long&>(d))
        : "l"(reinterpret_cast<unsigned long long&>(a)),
          "l"(reinterpret_cast<unsigned long long&>(b)),
          "l"(reinterpret_cast<unsigned long long&>(c)));
    return d;
}

__device__ __forceinline__ float softplusf(float z) {
    float a = fabsf(z);
    float e = __expf(-a);
    float l = __logf(1.0f + e);
    return fmaxf(z, 0.0f) + l;
}

// inclusive scan within 16-lane halves
__device__ __forceinline__ float scan16(float v, int yl) {
    #pragma unroll
    for (int off = 1; off < 16; off <<= 1) {
        float u = __shfl_up_sync(FULLM, v, off);
        if (yl >= off) v += u;
    }
    return v;
}

__global__ __launch_bounds__(BLOCK, 2)
void hist2d_inv_kernel(
    const float* __restrict__ wi,  const float* __restrict__ cond,
    const float* __restrict__ w0,  const float* __restrict__ b0,
    const float* __restrict__ w1,  const float* __restrict__ b1,
    const float* __restrict__ w2,  const float* __restrict__ b2,
    const float* __restrict__ w3,  const float* __restrict__ b3,
    float* __restrict__ out, int B)
{
    extern __shared__ float sm[];
    const int tid = threadIdx.x;

    // ---- cooperative weight staging (duplicated pairs for sample-packed FFMA2) ----
    float2* w0d = (float2*)(sm + OFF_W0D);
    float2* b0d = (float2*)(sm + OFF_B0D);
    float2* w1d = (float2*)(sm + OFF_W1D);
    float2* b1d = (float2*)(sm + OFF_B1D);
    float2* w2d = (float2*)(sm + OFF_W2D);
    float2* b2d = (float2*)(sm + OFF_B2D);
    float2* w3p = (float2*)(sm + OFF_W3P);
    float2* b3p = (float2*)(sm + OFF_B3P);

    for (int i = tid; i < CONDN*HID; i += BLOCK) { float v = w0[i]; w0d[i] = make_float2(v, v); }
    for (int i = tid; i < HID; i += BLOCK) {
        float v0 = b0[i], v1 = b1[i], v2 = b2[i];
        b0d[i] = make_float2(v0, v0);
        b1d[i] = make_float2(v1, v1);
        b2d[i] = make_float2(v2, v2);
    }
    for (int i = tid; i < HID*HID; i += BLOCK) {
        float v1 = w1[i], v2 = w2[i];
        w1d[i] = make_float2(v1, v1);
        w2d[i] = make_float2(v2, v2);
    }
    // w3 permuted into output pairs (m, m+32): w3p[k*128 + p*32 + j]
    for (int i = tid; i < HID*128; i += BLOCK) {
        int k = i >> 7, r = i & 127, p = r >> 5, j = r & 31;
        w3p[i] = make_float2(w3[k*NOUT + p*64 + j], w3[k*NOUT + p*64 + 32 + j]);
    }
    for (int i = tid; i < 128; i += BLOCK) {
        int p = i >> 5, j = i & 31;
        b3p[i] = make_float2(b3[p*64 + j], b3[p*64 + 32 + j]);
    }
    __syncthreads();

    const int lane = tid & 31;
    const int warp = tid >> 5;
    float*  wbase = sm + OFF_WARP + warp * WARP_SIZE_F;
    float2* smc2  = (float2*)(wbase + WARP_COND);   // [pair][10]
    float2* smh2  = (float2*)(wbase + WARP_H);      // [pair][32]
    float*  hist  = wbase + WARP_HIST;              // [T][320]

    const int gwarp  = blockIdx.x * WARPS + warp;
    const int nwarps = gridDim.x * WARPS;
    const int half = lane >> 4;
    const int yl   = lane & 15;
    const int base = half << 4;

    for (int s0 = gwarp * T; s0 < B; s0 += nwarps * T) {
        // ---- stage cond pairs: smc2[pr][i] = (cond[s0+2pr][i], cond[s0+2pr+1][i]) ----
        #pragma unroll
        for (int idx = lane; idx < T*CONDN; idx += 32) {
            int t = idx / CONDN, i = idx - t*CONDN;
            int s = min(s0 + t, B - 1);
            wbase[WARP_COND + ((t >> 1)*CONDN + i)*2 + (t & 1)] = cond[s*CONDN + i];
        }
        __syncwarp();

        // ---- layer 0: 10 -> 32, sample-packed FFMA2 ----
        {
            float2 acc[PAIRS];
            float2 bb = b0d[lane];
            #pragma unroll
            for (int pr = 0; pr < PAIRS; pr++) acc[pr] = bb;
            #pragma unroll
            for (int i = 0; i < CONDN; i++) {
                float2 wd = w0d[i*HID + lane];
                #pragma unroll
                for (int pr = 0; pr < PAIRS; pr++)
                    acc[pr] = ffma2(smc2[pr*CONDN + i], wd, acc[pr]);
            }
            __syncwarp();
            #pragma unroll
            for (int pr = 0; pr < PAIRS; pr++)
                smh2[pr*HID + lane] = make_float2(fmaxf(acc[pr].x, 0.0f), fmaxf(acc[pr].y, 0.0f));
            __syncwarp();
        }

        // ---- layers 1,2: 32 -> 32, sample-packed FFMA2, h via float4 broadcast ----
        #pragma unroll
        for (int L = 0; L < 2; L++) {
            float2* Wd = (L == 0) ? w1d : w2d;
            float2* Bd = (L == 0) ? b1d : b2d;
            float2 acc[PAIRS];
            float2 bb = Bd[lane];
            #pragma unroll
            for (int pr = 0; pr < PAIRS; pr++) acc[pr] = bb;
            #pragma unroll
            for (int k = 0; k < HID; k += 2) {
                float2 wd0 = Wd[k*HID + lane];
                float2 wd1 = Wd[(k+1)*HID + lane];
                #pragma unroll
                for (int pr = 0; pr < PAIRS; pr++) {
                    float4 hq = *(const float4*)(&smh2[pr*HID + k]);  // (hk.s0,hk.s1,hk1.s0,hk1.s1)
                    acc[pr] = ffma2(make_float2(hq.x, hq.y), wd0, acc[pr]);
                    acc[pr] = ffma2(make_float2(hq.z, hq.w), wd1, acc[pr]);
                }
            }
            __syncwarp();
            #pragma unroll
            for (int pr = 0; pr < PAIRS; pr++)
                smh2[pr*HID + lane] = make_float2(fmaxf(acc[pr].x, 0.0f), fmaxf(acc[pr].y, 0.0f));
            __syncwarp();
        }

        // ---- layer 3: 32 -> 256, output-packed FFMA2, h via float4 broadcast ----
        float2 acc3[T][4];
        #pragma unroll
        for (int p = 0; p < 4; p++) {
            float2 bb = b3p[p*32 + lane];
            #pragma unroll
            for (int t = 0; t < T; t++) acc3[t][p] = bb;
        }
        #pragma unroll 8
        for (int k = 0; k < HID; k += 2) {
            float2 wv0[4], wv1[4];
            #pragma unroll
            for (int p = 0; p < 4; p++) {
                wv0[p] = w3p[k*128 + p*32 + lane];
                wv1[p] = w3p[(k+1)*128 + p*32 + lane];
            }
            #pragma unroll
            for (int pr = 0; pr < PAIRS; pr++) {
                float4 hq = *(const float4*)(&smh2[pr*HID + k]);
                float2 ha = make_float2(hq.x, hq.x);
                float2 hb = make_float2(hq.y, hq.y);
                float2 hc = make_float2(hq.z, hq.z);
                float2 hd = make_float2(hq.w, hq.w);
                #pragma unroll
                for (int p = 0; p < 4; p++) {
                    acc3[2*pr  ][p] = ffma2(wv0[p], ha, acc3[2*pr  ][p]);
                    acc3[2*pr+1][p] = ffma2(wv0[p], hb, acc3[2*pr+1][p]);
                    acc3[2*pr  ][p] = ffma2(wv1[p], hc, acc3[2*pr  ][p]);
                    acc3[2*pr+1][p] = ffma2(wv1[p], hd, acc3[2*pr+1][p]);
                }
            }
        }

        __syncwarp();   // previous sampling-phase readers done before hist overwrite

        // ---- softplus + stage unnormalized hist ----
        #pragma unroll
        for (int t = 0; t < T; t++) {
            float* Ht = hist + t * HIST_STRIDE;
            #pragma unroll
            for (int p = 0; p < 4; p++) {
                float v0 = softplusf(acc3[t][p].x);   // m0 = p*64 + lane
                float v1 = softplusf(acc3[t][p].y);   // m1 = m0 + 32
                int m0 = p*64 + lane;
                Ht[(m0 >> 4)*HROW + (m0 & 15)] = v0;
                int m1 = m0 + 32;
                Ht[(m1 >> 4)*HROW + (m1 & 15)] = v1;
            }
        }
        __syncwarp();

        // ---- inverse-CDF sampling: 2 samples per pass on independent 16-lane halves ----
        #pragma unroll
        for (int it = 0; it < T/2; it++) {
            int t = 2*it + half;
            int s = s0 + t;
            bool valid = (s < B);
            int sc = min(s, B - 1);
            float2 uu = *(const float2*)(wi + 2*sc);
            float ux = uu.x, uy = uu.y;
            const float* Ht = hist + t * HIST_STRIDE;

            const float4* r4 = (const float4*)(Ht + yl*HROW);
            float4 a = r4[0], bq = r4[1], cq = r4[2], dq = r4[3];
            float rs = ((a.x + a.y) + (a.z + a.w)) + ((bq.x + bq.y) + (bq.z + bq.w))
                     + ((cq.x + cq.y) + (cq.z + cq.w)) + ((dq.x + dq.y) + (dq.z + dq.w));

            float C = scan16(rs, yl);                         // unnormalized cdf_y
            float S = __shfl_sync(FULLM, C, base + 15);
            float Sm = fmaxf(S, EPSF);
            float invS = 1.0f / Sm;
            float ty = uy * Sm;                               // C < uy*S  <=>  cdf_y < uy
            unsigned my = (__ballot_sync(FULLM, C < ty) >> base) & 0xFFFFu;
            int iy = __popc(my); if (iy > 15) iy = 15;
            float Cprev = __shfl_sync(FULLM, C, base + ((iy > 0) ? (iy - 1) : 0));
            if (iy == 0) Cprev = 0.0f;
            float py = __shfl_sync(FULLM, rs, base + iy);
            float yout = ((float)iy + (uy - Cprev*invS) / fmaxf(py*invS, EPSF)) * (1.0f/RES);

            float vr = Ht[iy*HROW + yl];
            float D = scan16(vr, yl);
            float tx = ux * py;                               // D < ux*py <=> cdf_x < ux
            unsigned mx = (__ballot_sync(FULLM, D < tx) >> base) & 0xFFFFu;
            int ix = __popc(mx); if (ix > 15) ix = 15;
            float Dprev = __shfl_sync(FULLM, D, base + ((ix > 0) ? (ix - 1) : 0));
            if (ix == 0) Dprev = 0.0f;
            float px = __shfl_sync(FULLM, vr, base + ix);
            float invpy = 1.0f / py;
            float xout = ((float)ix + (ux - Dprev*invpy) / fmaxf(px*invpy, EPSF)) * (1.0f/RES);
            float pdf = px * invS * ((float)(RES*RES) * 0.25f);

            if (valid && yl == 0) {
                *(float2*)(out + 2*s) = make_float2(xout*2.0f - 1.0f, yout*2.0f - 1.0f);
                out[2*B + s] = pdf;
            }
        }
    }
}

extern "C" void kernel_launch(void* const* d_in, const int* in_sizes, int n_in,
                              void* d_out, int out_size)
{
    const float* wi   = (const float*)d_in[0];
    const float* cond = (const float*)d_in[1];
    const float* w0   = (const float*)d_in[2];
    const float* b0   = (const float*)d_in[3];
    const float* w1   = (const float*)d_in[4];
    const float* b1   = (const float*)d_in[5];
    const float* w2   = (const float*)d_in[6];
    const float* b2   = (const float*)d_in[7];
    const float* w3   = (const float*)d_in[8];
    const float* b3   = (const float*)d_in[9];

    int B = in_sizes[0] / 2;

    cudaFuncSetAttribute(hist2d_inv_kernel,
                         cudaFuncAttributeMaxDynamicSharedMemorySize, SMEM_BYTES);

    // 2 CTAs/SM (99.8KB smem each) on 152-SM GB300
    hist2d_inv_kernel<<<304, BLOCK, SMEM_BYTES>>>(
        wi, cond, w0, b0, w1, b1, w2, b2, w3, b3, (float*)d_out, B);
}

// round 5
// speedup vs baseline: 1.3500x; 1.1658x over previous
#include <cuda_runtime.h>

#define RES    16
#define HID    32
#define CONDN  10
#define NOUT   256
#define BLOCK  128
#define WARPS  4
#define T      8
#define PAIRS  4
#define HSTAGE 4
#define FULLM  0xffffffffu
#define EPSF   1e-12f
#define HROW   20
#define HIST_STRIDE (RES*HROW)   // 320

// ---- shared layout (float offsets) ----
#define OFF_W0   0                     // 320
#define OFF_B0   (OFF_W0 + 320)       // 32
#define OFF_W1   (OFF_B0 + 32)        // 1024
#define OFF_B1   (OFF_W1 + 1024)      // 32
#define OFF_W2   (OFF_B1 + 32)        // 1024
#define OFF_B2   (OFF_W2 + 1024)      // 32
#define OFF_W3P  (OFF_B2 + 32)        // 8192 (float2 perm region)
#define OFF_B3P  (OFF_W3P + 8192)     // 256 (float2 perm region)
#define OFF_WARP (OFF_B3P + 256)      // 10912
#define WARP_COND 0                    // float2[4][10] = 80 f
#define WARP_H    80                   // float2[4][32] = 256 f
#define WARP_HIST 336                  // HSTAGE*320 = 1280 f
#define WARP_SIZE_F (WARP_HIST + HSTAGE*HIST_STRIDE)  // 1616 (mult of 4)
#define SMEM_FLOATS (OFF_WARP + WARPS*WARP_SIZE_F)    // 17376
#define SMEM_BYTES  (SMEM_FLOATS*4)                   // 69504 (67.9KB -> 3 CTAs/SM)

// packed fp32x2 FMA (sm_100+): FFMA2 in SASS
__device__ __forceinline__ float2 ffma2(float2 a, float2 b, float2 c) {
    float2 d;
    asm("fma.rn.f32x2 %0, %1, %2, %3;"
        : "=l"(reinterpret_cast<unsigned long long&>(d))
        : "l"(reinterpret_cast<unsigned long long&>(a)),
          "l"(reinterpret_cast<unsigned long long&>(b)),
          "l"(reinterpret_cast<unsigned long long&>(c)));
    return d;
}
__device__ __forceinline__ float2 dup2(float v) { return make_float2(v, v); }

__device__ __forceinline__ float softplusf(float z) {
    float a = fabsf(z);
    float e = __expf(-a);
    float l = __logf(1.0f + e);
    return fmaxf(z, 0.0f) + l;
}

// inclusive scan within 16-lane halves
__device__ __forceinline__ float scan16(float v, int yl) {
    #pragma unroll
    for (int off = 1; off < 16; off <<= 1) {
        float u = __shfl_up_sync(FULLM, v, off);
        if (yl >= off) v += u;
    }
    return v;
}

__global__ __launch_bounds__(BLOCK, 3)
void hist2d_inv_kernel(
    const float* __restrict__ wi,  const float* __restrict__ cond,
    const float* __restrict__ w0,  const float* __restrict__ b0,
    const float* __restrict__ w1,  const float* __restrict__ b1,
    const float* __restrict__ w2,  const float* __restrict__ b2,
    const float* __restrict__ w3,  const float* __restrict__ b3,
    float* __restrict__ out, int B)
{
    extern __shared__ float sm[];
    const int tid = threadIdx.x;

    float2* w3p = (float2*)(sm + OFF_W3P);
    float2* b3p = (float2*)(sm + OFF_B3P);

    // ---- cooperative weight staging (scalar for layers 0-2) ----
    for (int i = tid; i < CONDN*HID; i += BLOCK) sm[OFF_W0 + i] = w0[i];
    for (int i = tid; i < HID; i += BLOCK) {
        sm[OFF_B0 + i] = b0[i]; sm[OFF_B1 + i] = b1[i]; sm[OFF_B2 + i] = b2[i];
    }
    for (int i = tid; i < HID*HID; i += BLOCK) {
        sm[OFF_W1 + i] = w1[i]; sm[OFF_W2 + i] = w2[i];
    }
    // w3 permuted into output pairs (m, m+32): w3p[k*128 + p*32 + j]
    for (int i = tid; i < HID*128; i += BLOCK) {
        int k = i >> 7, r = i & 127, p = r >> 5, j = r & 31;
        w3p[i] = make_float2(w3[k*NOUT + p*64 + j], w3[k*NOUT + p*64 + 32 + j]);
    }
    for (int i = tid; i < 128; i += BLOCK) {
        int p = i >> 5, j = i & 31;
        b3p[i] = make_float2(b3[p*64 + j], b3[p*64 + 32 + j]);
    }
    __syncthreads();

    const int lane = tid & 31;
    const int warp = tid >> 5;
    float*  wbase = sm + OFF_WARP + warp * WARP_SIZE_F;
    float2* smc2  = (float2*)(wbase + WARP_COND);   // [pair][10]
    float2* smh2  = (float2*)(wbase + WARP_H);      // [pair][32]
    float*  hist  = wbase + WARP_HIST;              // [HSTAGE][320]

    const int gwarp  = blockIdx.x * WARPS + warp;
    const int nwarps = gridDim.x * WARPS;
    const int half = lane >> 4;
    const int yl   = lane & 15;
    const int base = half << 4;

    for (int s0 = gwarp * T; s0 < B; s0 += nwarps * T) {
        // ---- stage cond pairs: smc2[pr][i] = (cond[s0+2pr][i], cond[s0+2pr+1][i]) ----
        #pragma unroll
        for (int idx = lane; idx < T*CONDN; idx += 32) {
            int t = idx / CONDN, i = idx - t*CONDN;
            int s = min(s0 + t, B - 1);
            wbase[WARP_COND + ((t >> 1)*CONDN + i)*2 + (t & 1)] = cond[s*CONDN + i];
        }
        __syncwarp();

        // ---- layer 0: 10 -> 32, sample-packed FFMA2, scalar weights dup'd in regs ----
        {
            float2 acc[PAIRS];
            float2 bb = dup2(sm[OFF_B0 + lane]);
            #pragma unroll
            for (int pr = 0; pr < PAIRS; pr++) acc[pr] = bb;
            #pragma unroll
            for (int i = 0; i < CONDN; i++) {
                float2 wd = dup2(sm[OFF_W0 + i*HID + lane]);
                #pragma unroll
                for (int pr = 0; pr < PAIRS; pr++)
                    acc[pr] = ffma2(smc2[pr*CONDN + i], wd, acc[pr]);
            }
            __syncwarp();
            #pragma unroll
            for (int pr = 0; pr < PAIRS; pr++)
                smh2[pr*HID + lane] = make_float2(fmaxf(acc[pr].x, 0.0f), fmaxf(acc[pr].y, 0.0f));
            __syncwarp();
        }

        // ---- layers 1,2: 32 -> 32, sample-packed FFMA2, h via float4 broadcast ----
        #pragma unroll
        for (int L = 0; L < 2; L++) {
            const float* W  = sm + (L == 0 ? OFF_W1 : OFF_W2);
            const float* Bv = sm + (L == 0 ? OFF_B1 : OFF_B2);
            float2 acc[PAIRS];
            float2 bb = dup2(Bv[lane]);
            #pragma unroll
            for (int pr = 0; pr < PAIRS; pr++) acc[pr] = bb;
            #pragma unroll
            for (int k = 0; k < HID; k += 2) {
                float2 wd0 = dup2(W[k*HID + lane]);
                float2 wd1 = dup2(W[(k+1)*HID + lane]);
                #pragma unroll
                for (int pr = 0; pr < PAIRS; pr++) {
                    float4 hq = *(const float4*)(&smh2[pr*HID + k]);  // (hk.s0,hk.s1,hk1.s0,hk1.s1)
                    acc[pr] = ffma2(make_float2(hq.x, hq.y), wd0, acc[pr]);
                    acc[pr] = ffma2(make_float2(hq.z, hq.w), wd1, acc[pr]);
                }
            }
            __syncwarp();
            #pragma unroll
            for (int pr = 0; pr < PAIRS; pr++)
                smh2[pr*HID + lane] = make_float2(fmaxf(acc[pr].x, 0.0f), fmaxf(acc[pr].y, 0.0f));
            __syncwarp();
        }

        // ---- layer 3: 32 -> 256, output-packed FFMA2, h via float4 broadcast ----
        float2 acc3[T][4];
        #pragma unroll
        for (int p = 0; p < 4; p++) {
            float2 bb = b3p[p*32 + lane];
            #pragma unroll
            for (int t = 0; t < T; t++) acc3[t][p] = bb;
        }
        #pragma unroll 8
        for (int k = 0; k < HID; k += 2) {
            float2 wv0[4], wv1[4];
            #pragma unroll
            for (int p = 0; p < 4; p++) {
                wv0[p] = w3p[k*128 + p*32 + lane];
                wv1[p] = w3p[(k+1)*128 + p*32 + lane];
            }
            #pragma unroll
            for (int pr = 0; pr < PAIRS; pr++) {
                float4 hq = *(const float4*)(&smh2[pr*HID + k]);
                float2 ha = make_float2(hq.x, hq.x);
                float2 hb = make_float2(hq.y, hq.y);
                float2 hc = make_float2(hq.z, hq.z);
                float2 hd = make_float2(hq.w, hq.w);
                #pragma unroll
                for (int p = 0; p < 4; p++) {
                    acc3[2*pr  ][p] = ffma2(wv0[p], ha, acc3[2*pr  ][p]);
                    acc3[2*pr+1][p] = ffma2(wv0[p], hb, acc3[2*pr+1][p]);
                    acc3[2*pr  ][p] = ffma2(wv1[p], hc, acc3[2*pr  ][p]);
                    acc3[2*pr+1][p] = ffma2(wv1[p], hd, acc3[2*pr+1][p]);
                }
            }
        }

        // ---- two phases: stage HSTAGE hists, then sample them ----
        #pragma unroll
        for (int ph = 0; ph < T/HSTAGE; ph++) {
            __syncwarp();   // prior readers of hist done
            #pragma unroll
            for (int tt = 0; tt < HSTAGE; tt++) {
                int t = ph*HSTAGE + tt;
                float* Ht = hist + tt * HIST_STRIDE;
                #pragma unroll
                for (int p = 0; p < 4; p++) {
                    float v0 = softplusf(acc3[t][p].x);   // m0 = p*64 + lane
                    float v1 = softplusf(acc3[t][p].y);   // m1 = m0 + 32
                    int m0 = p*64 + lane;
                    Ht[(m0 >> 4)*HROW + (m0 & 15)] = v0;
                    int m1 = m0 + 32;
                    Ht[(m1 >> 4)*HROW + (m1 & 15)] = v1;
                }
            }
            __syncwarp();

            // 2 samples per pass on independent 16-lane halves
            #pragma unroll
            for (int it = 0; it < HSTAGE/2; it++) {
                int tt = 2*it + half;
                int s = s0 + ph*HSTAGE + tt;
                bool valid = (s < B);
                int sc = min(s, B - 1);
                float2 uu = *(const float2*)(wi + 2*sc);
                float ux = uu.x, uy = uu.y;
                const float* Ht = hist + tt * HIST_STRIDE;

                const float4* r4 = (const float4*)(Ht + yl*HROW);
                float4 a = r4[0], bq = r4[1], cq = r4[2], dq = r4[3];
                float rs = ((a.x + a.y) + (a.z + a.w)) + ((bq.x + bq.y) + (bq.z + bq.w))
                         + ((cq.x + cq.y) + (cq.z + cq.w)) + ((dq.x + dq.y) + (dq.z + dq.w));

                float C = scan16(rs, yl);                         // unnormalized cdf_y
                float S = __shfl_sync(FULLM, C, base + 15);
                float Sm = fmaxf(S, EPSF);
                float invS = 1.0f / Sm;
                float ty = uy * Sm;                               // C < uy*S <=> cdf_y < uy
                unsigned my = (__ballot_sync(FULLM, C < ty) >> base) & 0xFFFFu;
                int iy = __popc(my); if (iy > 15) iy = 15;
                float Cprev = __shfl_sync(FULLM, C, base + ((iy > 0) ? (iy - 1) : 0));
                if (iy == 0) Cprev = 0.0f;
                float py = __shfl_sync(FULLM, rs, base + iy);
                float yout = ((float)iy + (uy - Cprev*invS) / fmaxf(py*invS, EPSF)) * (1.0f/RES);

                float vr = Ht[iy*HROW + yl];
                float D = scan16(vr, yl);
                float tx = ux * py;                               // D < ux*py <=> cdf_x < ux
                unsigned mx = (__ballot_sync(FULLM, D < tx) >> base) & 0xFFFFu;
                int ix = __popc(mx); if (ix > 15) ix = 15;
                float Dprev = __shfl_sync(FULLM, D, base + ((ix > 0) ? (ix - 1) : 0));
                if (ix == 0) Dprev = 0.0f;
                float px = __shfl_sync(FULLM, vr, base + ix);
                float invpy = 1.0f / py;
                float xout = ((float)ix + (ux - Dprev*invpy) / fmaxf(px*invpy, EPSF)) * (1.0f/RES);
                float pdf = px * invS * ((float)(RES*RES) * 0.25f);

                if (valid && yl == 0) {
                    *(float2*)(out + 2*s) = make_float2(xout*2.0f - 1.0f, yout*2.0f - 1.0f);
                    out[2*B + s] = pdf;
                }
            }
        }
    }
}

extern "C" void kernel_launch(void* const* d_in, const int* in_sizes, int n_in,
                              void* d_out, int out_size)
{
    const float* wi   = (const float*)d_in[0];
    const float* cond = (const float*)d_in[1];
    const float* w0   = (const float*)d_in[2];
    const float* b0   = (const float*)d_in[3];
    const float* w1   = (const float*)d_in[4];
    const float* b1   = (const float*)d_in[5];
    const float* w2   = (const float*)d_in[6];
    const float* b2   = (const float*)d_in[7];
    const float* w3   = (const float*)d_in[8];
    const float* b3   = (const float*)d_in[9];

    int B = in_sizes[0] / 2;

    cudaFuncSetAttribute(hist2d_inv_kernel,
                         cudaFuncAttributeMaxDynamicSharedMemorySize, SMEM_BYTES);

    // 3 CTAs/SM (67.9KB smem each) on 152-SM GB300
    hist2d_inv_kernel<<<456, BLOCK, SMEM_BYTES>>>(
        wi, cond, w0, b0, w1, b1, w2, b2, w3, b3, (float*)d_out, B);
}

// round 13
// speedup vs baseline: 1.3943x; 1.0328x over previous
#include <cuda_runtime.h>

#define RES    16
#define HID    32
#define CONDN  10
#define NOUT   256
#define BLOCK  256
#define WARPS  8
#define T      8
#define PAIRS  4
#define HSTAGE 4
#define FULLM  0xffffffffu
#define EPSF   1e-12f
#define HROW   20
#define HIST_STRIDE (RES*HROW)   // 320

// ---- shared layout (float offsets) ----
#define OFF_W0   0                     // 320
#define OFF_W1   (OFF_W0 + 320)       // 1024
#define OFF_W2   (OFF_W1 + 1024)      // 1024
#define OFF_W3P  (OFF_W2 + 1024)      // 8192 (float2 perm region), offset 2368
#define OFF_WARP (OFF_W3P + 8192)     // 10560
#define WARP_COND 0                    // float2[4][10] = 80 f
#define WARP_HIST 80                   // HSTAGE*320 = 1280 f ; smh2 aliases first 256 f
#define WARP_SIZE_F (WARP_HIST + HSTAGE*HIST_STRIDE)  // 1360 (mult of 4)
#define SMEM_FLOATS (OFF_WARP + WARPS*WARP_SIZE_F)    // 21440
#define SMEM_BYTES  (SMEM_FLOATS*4)                   // 85760 B = 83.75KB -> 2 CTAs/SM

// packed fp32x2 FMA (sm_100+): FFMA2 in SASS
__device__ __forceinline__ float2 ffma2(float2 a, float2 b, float2 c) {
    float2 d;
    asm("fma.rn.f32x2 %0, %1, %2, %3;"
        : "=l"(reinterpret_cast<unsigned long long&>(d))
        : "l"(reinterpret_cast<unsigned long long&>(a)),
          "l"(reinterpret_cast<unsigned long long&>(b)),
          "l"(reinterpret_cast<unsigned long long&>(c)));
    return d;
}
__device__ __forceinline__ float2 dup2(float v) { return make_float2(v, v); }

__device__ __forceinline__ float softplusf(float z) {
    float a = fabsf(z);
    float e = __expf(-a);
    float l = __logf(1.0f + e);
    return fmaxf(z, 0.0f) + l;
}

// inclusive scan within 16-lane halves
__device__ __forceinline__ float scan16(float v, int yl) {
    #pragma unroll
    for (int off = 1; off < 16; off <<= 1) {
        float u = __shfl_up_sync(FULLM, v, off);
        if (yl >= off) v += u;
    }
    return v;
}

__global__ __launch_bounds__(BLOCK, 2)
void hist2d_inv_kernel(
    const float* __restrict__ wi,  const float* __restrict__ cond,
    const float* __restrict__ w0,  const float* __restrict__ b0,
    const float* __restrict__ w1,  const float* __restrict__ b1,
    const float* __restrict__ w2,  const float* __restrict__ b2,
    const float* __restrict__ w3,  const float* __restrict__ b3,
    float* __restrict__ out, int B)
{
    extern __shared__ float sm[];
    const int tid = threadIdx.x;

    float2* w3p = (float2*)(sm + OFF_W3P);

    // ---- cooperative weight staging (scalar for layers 0-2; biases stay in regs) ----
    for (int i = tid; i < CONDN*HID; i += BLOCK) sm[OFF_W0 + i] = w0[i];
    for (int i = tid; i < HID*HID; i += BLOCK) {
        sm[OFF_W1 + i] = w1[i]; sm[OFF_W2 + i] = w2[i];
    }
    // w3 permuted into output pairs (m, m+32): w3p[k*128 + p*32 + j]
    for (int i = tid; i < HID*128; i += BLOCK) {
        int k = i >> 7, r = i & 127, p = r >> 5, j = r & 31;
        w3p[i] = make_float2(w3[k*NOUT + p*64 + j], w3[k*NOUT + p*64 + 32 + j]);
    }
    __syncthreads();

    const int lane = tid & 31;
    const int warp = tid >> 5;
    float*  wbase = sm + OFF_WARP + warp * WARP_SIZE_F;
    float2* smc2  = (float2*)(wbase + WARP_COND);   // [pair][10]
    float2* smh2  = (float2*)(wbase + WARP_HIST);   // aliases hist slot 0 (dead before hist writes)
    float*  hist  = wbase + WARP_HIST;              // [HSTAGE][320]

    // ---- lane-invariant biases hoisted to registers (one-time LDG) ----
    const float2 bb0 = dup2(b0[lane]);
    const float2 bb1 = dup2(b1[lane]);
    const float2 bb2 = dup2(b2[lane]);
    float2 b3r[4];
    #pragma unroll
    for (int p = 0; p < 4; p++)
        b3r[p] = make_float2(b3[p*64 + lane], b3[p*64 + 32 + lane]);

    const int gwarp  = blockIdx.x * WARPS + warp;
    const int nwarps = gridDim.x * WARPS;
    const int half = lane >> 4;
    const int yl   = lane & 15;
    const int base = half << 4;

    for (int s0 = gwarp * T; s0 < B; s0 += nwarps * T) {
        // ---- stage cond pairs: smc2[pr][i] = (cond[s0+2pr][i], cond[s0+2pr+1][i]) ----
        #pragma unroll
        for (int idx = lane; idx < T*CONDN; idx += 32) {
            int t = idx / CONDN, i = idx - t*CONDN;
            int s = min(s0 + t, B - 1);
            wbase[WARP_COND + ((t >> 1)*CONDN + i)*2 + (t & 1)] = cond[s*CONDN + i];
        }
        __syncwarp();

        // ---- layer 0: 10 -> 32, sample-packed FFMA2, scalar weights dup'd in regs ----
        {
            float2 acc[PAIRS];
            #pragma unroll
            for (int pr = 0; pr < PAIRS; pr++) acc[pr] = bb0;
            #pragma unroll
            for (int i = 0; i < CONDN; i++) {
                float2 wd = dup2(sm[OFF_W0 + i*HID + lane]);
                #pragma unroll
                for (int pr = 0; pr < PAIRS; pr++)
                    acc[pr] = ffma2(smc2[pr*CONDN + i], wd, acc[pr]);
            }
            __syncwarp();   // also orders prev-iteration hist reads before smh2 overwrite
            #pragma unroll
            for (int pr = 0; pr < PAIRS; pr++)
                smh2[pr*HID + lane] = make_float2(fmaxf(acc[pr].x, 0.0f), fmaxf(acc[pr].y, 0.0f));
            __syncwarp();
        }

        // ---- layers 1,2: 32 -> 32, sample-packed FFMA2, h via float4 broadcast ----
        #pragma unroll
        for (int L = 0; L < 2; L++) {
            const float* W = sm + (L == 0 ? OFF_W1 : OFF_W2);
            float2 acc[PAIRS];
            float2 bbL = (L == 0) ? bb1 : bb2;
            #pragma unroll
            for (int pr = 0; pr < PAIRS; pr++) acc[pr] = bbL;
            #pragma unroll
            for (int k = 0; k < HID; k += 2) {
                float2 wd0 = dup2(W[k*HID + lane]);
                float2 wd1 = dup2(W[(k+1)*HID + lane]);
                #pragma unroll
                for (int pr = 0; pr < PAIRS; pr++) {
                    float4 hq = *(const float4*)(&smh2[pr*HID + k]);  // (hk.s0,hk.s1,hk1.s0,hk1.s1)
                    acc[pr] = ffma2(make_float2(hq.x, hq.y), wd0, acc[pr]);
                    acc[pr] = ffma2(make_float2(hq.z, hq.w), wd1, acc[pr]);
                }
            }
            __syncwarp();
            #pragma unroll
            for (int pr = 0; pr < PAIRS; pr++)
                smh2[pr*HID + lane] = make_float2(fmaxf(acc[pr].x, 0.0f), fmaxf(acc[pr].y, 0.0f));
            __syncwarp();
        }

        // ---- layer 3: 32 -> 256, output-packed FFMA2, h via float4 broadcast ----
        float2 acc3[T][4];
        #pragma unroll
        for (int p = 0; p < 4; p++) {
            #pragma unroll
            for (int t = 0; t < T; t++) acc3[t][p] = b3r[p];
        }
        #pragma unroll 8
        for (int k = 0; k < HID; k += 2) {
            float2 wv0[4], wv1[4];
            #pragma unroll
            for (int p = 0; p < 4; p++) {
                wv0[p] = w3p[k*128 + p*32 + lane];
                wv1[p] = w3p[(k+1)*128 + p*32 + lane];
            }
            #pragma unroll
            for (int pr = 0; pr < PAIRS; pr++) {
                float4 hq = *(const float4*)(&smh2[pr*HID + k]);
                float2 ha = make_float2(hq.x, hq.x);
                float2 hb = make_float2(hq.y, hq.y);
                float2 hc = make_float2(hq.z, hq.z);
                float2 hd = make_float2(hq.w, hq.w);
                #pragma unroll
                for (int p = 0; p < 4; p++) {
                    acc3[2*pr  ][p] = ffma2(wv0[p], ha, acc3[2*pr  ][p]);
                    acc3[2*pr+1][p] = ffma2(wv0[p], hb, acc3[2*pr+1][p]);
                    acc3[2*pr  ][p] = ffma2(wv1[p], hc, acc3[2*pr  ][p]);
                    acc3[2*pr+1][p] = ffma2(wv1[p], hd, acc3[2*pr+1][p]);
                }
            }
        }

        // ---- two phases: stage HSTAGE hists, then sample them ----
        #pragma unroll
        for (int ph = 0; ph < T/HSTAGE; ph++) {
            __syncwarp();   // prior readers of hist (and smh2 on ph=0) done
            #pragma unroll
            for (int tt = 0; tt < HSTAGE; tt++) {
                int t = ph*HSTAGE + tt;
                float* Ht = hist + tt * HIST_STRIDE;
                #pragma unroll
                for (int p = 0; p < 4; p++) {
                    float v0 = softplusf(acc3[t][p].x);   // m0 = p*64 + lane
                    float v1 = softplusf(acc3[t][p].y);   // m1 = m0 + 32
                    int m0 = p*64 + lane;
                    Ht[(m0 >> 4)*HROW + (m0 & 15)] = v0;
                    int m1 = m0 + 32;
                    Ht[(m1 >> 4)*HROW + (m1 & 15)] = v1;
                }
            }
            __syncwarp();

            // 2 samples per pass on independent 16-lane halves
            #pragma unroll
            for (int it = 0; it < HSTAGE/2; it++) {
                int tt = 2*it + half;
                int s = s0 + ph*HSTAGE + tt;
                bool valid = (s < B);
                int sc = min(s, B - 1);
                float2 uu = *(const float2*)(wi + 2*sc);
                float ux = uu.x, uy = uu.y;
                const float* Ht = hist + tt * HIST_STRIDE;

                const float4* r4 = (const float4*)(Ht + yl*HROW);
                float4 a = r4[0], bq = r4[1], cq = r4[2], dq = r4[3];
                float rs = ((a.x + a.y) + (a.z + a.w)) + ((bq.x + bq.y) + (bq.z + bq.w))
                         + ((cq.x + cq.y) + (cq.z + cq.w)) + ((dq.x + dq.y) + (dq.z + dq.w));

                float C = scan16(rs, yl);                         // unnormalized cdf_y
                float S = __shfl_sync(FULLM, C, base + 15);
                float Sm = fmaxf(S, EPSF);
                float invS = 1.0f / Sm;
                float ty = uy * Sm;                               // C < uy*S <=> cdf_y < uy
                unsigned my = (__ballot_sync(FULLM, C < ty) >> base) & 0xFFFFu;
                int iy = __popc(my); if (iy > 15) iy = 15;
                float Cprev = __shfl_sync(FULLM, C, base + ((iy > 0) ? (iy - 1) : 0));
                if (iy == 0) Cprev = 0.0f;
                float py = __shfl_sync(FULLM, rs, base + iy);
                float yout = ((float)iy + (uy - Cprev*invS) / fmaxf(py*invS, EPSF)) * (1.0f/RES);

                float vr = Ht[iy*HROW + yl];
                float D = scan16(vr, yl);
                float tx = ux * py;                               // D < ux*py <=> cdf_x < ux
                unsigned mx = (__ballot_sync(FULLM, D < tx) >> base) & 0xFFFFu;
                int ix = __popc(mx); if (ix > 15) ix = 15;
                float Dprev = __shfl_sync(FULLM, D, base + ((ix > 0) ? (ix - 1) : 0));
                if (ix == 0) Dprev = 0.0f;
                float px = __shfl_sync(FULLM, vr, base + ix);
                float invpy = 1.0f / py;
                float xout = ((float)ix + (ux - Dprev*invpy) / fmaxf(px*invpy, EPSF)) * (1.0f/RES);
                float pdf = px * invS * ((float)(RES*RES) * 0.25f);

                if (valid && yl == 0) {
                    *(float2*)(out + 2*s) = make_float2(xout*2.0f - 1.0f, yout*2.0f - 1.0f);
                    out[2*B + s] = pdf;
                }
            }
        }
    }
}

extern "C" void kernel_launch(void* const* d_in, const int* in_sizes, int n_in,
                              void* d_out, int out_size)
{
    const float* wi   = (const float*)d_in[0];
    const float* cond = (const float*)d_in[1];
    const float* w0   = (const float*)d_in[2];
    const float* b0   = (const float*)d_in[3];
    const float* w1   = (const float*)d_in[4];
    const float* b1   = (const float*)d_in[5];
    const float* w2   = (const float*)d_in[6];
    const float* b2   = (const float*)d_in[7];
    const float* w3   = (const float*)d_in[8];
    const float* b3   = (const float*)d_in[9];

    int B = in_sizes[0] / 2;

    cudaFuncSetAttribute(hist2d_inv_kernel,
                         cudaFuncAttributeMaxDynamicSharedMemorySize, SMEM_BYTES);

    // 2 CTAs/SM x 256 threads = 16 warps/SM on 152-SM GB300
    hist2d_inv_kernel<<<304, BLOCK, SMEM_BYTES>>>(
        wi, cond, w0, b0, w1, b1, w2, b2, w3, b3, (float*)d_out, B);
}